// round 7
// baseline (speedup 1.0000x reference)
#include <cuda_runtime.h>

// SpectralConv2D fused kernel, R7 = R6 + 16B-aligned smem (R6 trapped on a
// misaligned float4 store into a 4B-aligned float array).
//   up[b,n]    = mean_c inputs[b,n,c]
//   base[f,p]  = omega[f,i,j] * (lambda_in[i]-lambda_out[j]), p=i*3+j
//   out[b,l,f] = relu( sum_p base[f,p] * (enc[n]-dec[l]) * up[b,n] )

#define B_    64
#define W_    32
#define C_    8
#define F_    64
#define O2_   30
#define L_    900
#define N_    1024
#define TILE  30          // one output row; 3 input rows

// per-tap LUTs: p=i*3+j; sel: 0=diag,1=triu,2=tril; t: index within src row
__constant__ int c_sel[9] = {0,1,1,2,0,1,2,2,0};
__constant__ int c_t  [9] = {0,0,1,0,1,2,1,2,2};
__constant__ int c_i  [9] = {0,0,0,1,1,1,2,2,2};
__constant__ int c_j  [9] = {0,1,2,0,1,2,0,1,2};

__global__ __launch_bounds__(128, 6)
void spectral_fused_kernel(
    const float* __restrict__ inputs,      // (B, 32, 32, 8)
    const float* __restrict__ omega_diag,  // (F, 3)
    const float* __restrict__ omega_triu,  // (F*3)
    const float* __restrict__ omega_tril,  // (F*3)
    const float* __restrict__ lambda_in,   // (3)
    const float* __restrict__ lambda_out,  // (3)
    const float* __restrict__ use_encode,  // (N)
    const float* __restrict__ use_decode,  // (L)
    float* __restrict__ out)               // (B, L, F)
{
    __shared__ __align__(16) float  up_s[96];        // 3 input rows x 32 cols
    __shared__ __align__(16) float  eu_s[96];        // enc*up
    __shared__ __align__(16) float  dec_s[32];
    __shared__ __align__(16) float  base_s[9 * F_];  // [p][f]
    __shared__ float4 y_s[TILE * 3];                  // [pos][3 x float4]

    const int tid = threadIdx.x;
    const int r0  = blockIdx.x;            // output row 0..29
    const int b   = blockIdx.y;
    const int l0  = r0 * O2_;

    // ---------------- Phase A: input reduce + dec ----------------
    if (tid < 96) {
        int n = (r0 + (tid >> 5)) * W_ + (tid & 31);
        const float4* p = (const float4*)(inputs + ((size_t)b * N_ + n) * C_);
        float4 v0 = p[0];
        float4 v1 = p[1];
        float m = (v0.x + v0.y + v0.z + v0.w + v1.x + v1.y + v1.z + v1.w) * 0.125f;
        up_s[tid] = m;
        eu_s[tid] = m * __ldg(&use_encode[n]);
    } else if (tid < 96 + TILE) {
        dec_s[tid - 96] = __ldg(&use_decode[l0 + tid - 96]);
    }

    // branchless base assembly: 576 entries over 128 threads
    {
        const float* srcs[3] = { omega_diag, omega_triu, omega_tril };
        #pragma unroll
        for (int k = 0; k < 5; k++) {
            int idx = tid + k * 128;
            if (k < 4 || tid < 64) {
                int pp = idx >> 6;
                int f  = idx & 63;
                float w = __ldg(&srcs[c_sel[pp]][f * 3 + c_t[pp]]);
                float lam = __ldg(&lambda_in[c_i[pp]]) - __ldg(&lambda_out[c_j[pp]]);
                base_s[idx] = w * lam;
            }
        }
    }
    __syncthreads();

    // ---------------- Phase B: y[pos][9], one thread per position ----------------
    if (tid < TILE) {
        float dec = dec_s[tid];
        int i0 = tid;                      // local col; rows 0..2 at stride 32
        float4 ya, yb, yc;
        ya.x = eu_s[i0 +  0] - dec * up_s[i0 +  0];
        ya.y = eu_s[i0 +  1] - dec * up_s[i0 +  1];
        ya.z = eu_s[i0 +  2] - dec * up_s[i0 +  2];
        ya.w = eu_s[i0 + 32] - dec * up_s[i0 + 32];
        yb.x = eu_s[i0 + 33] - dec * up_s[i0 + 33];
        yb.y = eu_s[i0 + 34] - dec * up_s[i0 + 34];
        yb.z = eu_s[i0 + 64] - dec * up_s[i0 + 64];
        yb.w = eu_s[i0 + 65] - dec * up_s[i0 + 65];
        yc.x = eu_s[i0 + 66] - dec * up_s[i0 + 66];
        yc.y = 0.f; yc.z = 0.f; yc.w = 0.f;
        y_s[tid * 3 + 0] = ya;
        y_s[tid * 3 + 1] = yb;
        y_s[tid * 3 + 2] = yc;
    }

    // prefetch weights while Phase B runs (base_s final since sync1)
    const int f4 = tid & 15;
    const int g  = tid >> 4;               // 0..7
    float4 w[9];
    #pragma unroll
    for (int pp = 0; pp < 9; pp++)
        w[pp] = *(const float4*)(base_s + pp * F_ + f4 * 4);

    __syncthreads();

    // ---------------- Phase C: 4 positions per thread ----------------
    float* obase = out + ((size_t)b * L_ + l0) * F_;
    #pragma unroll
    for (int k2 = 0; k2 < 4; k2++) {
        int pos = g + k2 * 8;              // 0..31, predicate off 30,31
        if (pos < TILE) {
            float4 ya = y_s[pos * 3 + 0];
            float4 yb = y_s[pos * 3 + 1];
            float4 yc = y_s[pos * 3 + 2];
            float y[9] = { ya.x, ya.y, ya.z, ya.w, yb.x, yb.y, yb.z, yb.w, yc.x };

            float4 acc = make_float4(0.f, 0.f, 0.f, 0.f);
            #pragma unroll
            for (int pp = 0; pp < 9; pp++) {
                acc.x = fmaf(w[pp].x, y[pp], acc.x);
                acc.y = fmaf(w[pp].y, y[pp], acc.y);
                acc.z = fmaf(w[pp].z, y[pp], acc.z);
                acc.w = fmaf(w[pp].w, y[pp], acc.w);
            }
            acc.x = fmaxf(acc.x, 0.f);
            acc.y = fmaxf(acc.y, 0.f);
            acc.z = fmaxf(acc.z, 0.f);
            acc.w = fmaxf(acc.w, 0.f);

            ((float4*)(obase + pos * F_))[f4] = acc;
        }
    }
}

extern "C" void kernel_launch(void* const* d_in, const int* in_sizes, int n_in,
                              void* d_out, int out_size) {
    (void)in_sizes; (void)n_in; (void)out_size;
    const float* inputs      = (const float*)d_in[0];
    const float* omega_diag  = (const float*)d_in[1];
    const float* omega_triu  = (const float*)d_in[2];
    const float* omega_tril  = (const float*)d_in[3];
    const float* lambda_in   = (const float*)d_in[4];
    const float* lambda_out  = (const float*)d_in[5];
    const float* use_encode  = (const float*)d_in[6];
    const float* use_decode  = (const float*)d_in[7];
    float* out = (float*)d_out;

    dim3 grid(O2_, B_);   // (30, 64) = 1920 blocks
    spectral_fused_kernel<<<grid, 128>>>(
        inputs, omega_diag, omega_triu, omega_tril,
        lambda_in, lambda_out, use_encode, use_decode, out);
}